// round 3
// baseline (speedup 1.0000x reference)
#include <cuda_runtime.h>
#include <math.h>

#define KP 16384
#define DP 2048
#define DECAYF 0.99f
#define THRESHF 0.5f

// __device__ scratch (no allocations allowed)
__device__ float g_dot[KP];     // z . p_i
__device__ float g_pn2[KP];     // ||p_i||^2
__device__ float g_logits[KP];  // first logits
__device__ float g_l2[KP];      // logits2
__device__ float g_a[KP];       // EMA coef of z
__device__ float g_b[KP];       // EMA coef of p
__device__ int   g_evict;
__device__ int   g_evict_idx;

// ---------------- kernel 1: per-row dot + norm (high-MLP) ----------------
__global__ void k1_dots(const float* __restrict__ z, const float* __restrict__ p) {
    __shared__ float4 zs[DP / 4];
    for (int i = threadIdx.x; i < DP / 4; i += blockDim.x)
        zs[i] = ((const float4*)z)[i];
    __syncthreads();
    int warp = threadIdx.x >> 5, lane = threadIdx.x & 31;
    int row = (blockIdx.x << 3) + warp;  // 8 warps/block
    const float4* pr = (const float4*)(p + (size_t)row * DP);
    float dot = 0.f, n2 = 0.f;
    // 16 float4 per lane; batch 4 loads back-to-back for MLP
    #pragma unroll
    for (int it = 0; it < 4; ++it) {
        float4 a0 = pr[lane + (it * 4 + 0) * 32];
        float4 a1 = pr[lane + (it * 4 + 1) * 32];
        float4 a2 = pr[lane + (it * 4 + 2) * 32];
        float4 a3 = pr[lane + (it * 4 + 3) * 32];
        float4 b0 = zs[lane + (it * 4 + 0) * 32];
        float4 b1 = zs[lane + (it * 4 + 1) * 32];
        float4 b2 = zs[lane + (it * 4 + 2) * 32];
        float4 b3 = zs[lane + (it * 4 + 3) * 32];
        dot += a0.x * b0.x + a0.y * b0.y + a0.z * b0.z + a0.w * b0.w;
        n2  += a0.x * a0.x + a0.y * a0.y + a0.z * a0.z + a0.w * a0.w;
        dot += a1.x * b1.x + a1.y * b1.y + a1.z * b1.z + a1.w * b1.w;
        n2  += a1.x * a1.x + a1.y * a1.y + a1.z * a1.z + a1.w * a1.w;
        dot += a2.x * b2.x + a2.y * b2.y + a2.z * b2.z + a2.w * b2.w;
        n2  += a2.x * a2.x + a2.y * a2.y + a2.z * a2.z + a2.w * a2.w;
        dot += a3.x * b3.x + a3.y * b3.y + a3.z * b3.z + a3.w * b3.w;
        n2  += a3.x * a3.x + a3.y * a3.y + a3.z * a3.z + a3.w * a3.w;
    }
    #pragma unroll
    for (int o = 16; o; o >>= 1) {
        dot += __shfl_down_sync(0xffffffffu, dot, o);
        n2  += __shfl_down_sync(0xffffffffu, n2, o);
    }
    if (lane == 0) { g_dot[row] = dot; g_pn2[row] = n2; }
}

// ---------------- block reduction helpers (blockDim = 1024) ----------------
__device__ __forceinline__ float block_sum(float v, float* red) {
    int lane = threadIdx.x & 31, w = threadIdx.x >> 5;
    #pragma unroll
    for (int o = 16; o; o >>= 1) v += __shfl_down_sync(0xffffffffu, v, o);
    if (lane == 0) red[w] = v;
    __syncthreads();
    if (w == 0) {
        v = red[lane];
        #pragma unroll
        for (int o = 16; o; o >>= 1) v += __shfl_down_sync(0xffffffffu, v, o);
        if (lane == 0) red[0] = v;
    }
    __syncthreads();
    float r = red[0];
    __syncthreads();
    return r;
}

__device__ __forceinline__ float block_max(float v, float* red) {
    int lane = threadIdx.x & 31, w = threadIdx.x >> 5;
    #pragma unroll
    for (int o = 16; o; o >>= 1) v = fmaxf(v, __shfl_down_sync(0xffffffffu, v, o));
    if (lane == 0) red[w] = v;
    __syncthreads();
    if (w == 0) {
        v = red[lane];
        #pragma unroll
        for (int o = 16; o; o >>= 1) v = fmaxf(v, __shfl_down_sync(0xffffffffu, v, o));
        if (lane == 0) red[0] = v;
    }
    __syncthreads();
    float r = red[0];
    __syncthreads();
    return r;
}

// argmax with first-occurrence (lowest index) tie-break
__device__ __forceinline__ void block_argmax(float v, int idx, float* red, int* redi,
                                             float* ov, int* oi) {
    int lane = threadIdx.x & 31, w = threadIdx.x >> 5;
    #pragma unroll
    for (int o = 16; o; o >>= 1) {
        float v2 = __shfl_down_sync(0xffffffffu, v, o);
        int   i2 = __shfl_down_sync(0xffffffffu, idx, o);
        if (v2 > v || (v2 == v && i2 < idx)) { v = v2; idx = i2; }
    }
    if (lane == 0) { red[w] = v; redi[w] = idx; }
    __syncthreads();
    if (w == 0) {
        v = red[lane]; idx = redi[lane];
        #pragma unroll
        for (int o = 16; o; o >>= 1) {
            float v2 = __shfl_down_sync(0xffffffffu, v, o);
            int   i2 = __shfl_down_sync(0xffffffffu, idx, o);
            if (v2 > v || (v2 == v && i2 < idx)) { v = v2; idx = i2; }
        }
        if (lane == 0) { red[0] = v; redi[0] = idx; }
    }
    __syncthreads();
    *ov = red[0]; *oi = redi[0];
    __syncthreads();
}

// argmin with first-occurrence tie-break
__device__ __forceinline__ void block_argmin(float v, int idx, float* red, int* redi,
                                             float* ov, int* oi) {
    int lane = threadIdx.x & 31, w = threadIdx.x >> 5;
    #pragma unroll
    for (int o = 16; o; o >>= 1) {
        float v2 = __shfl_down_sync(0xffffffffu, v, o);
        int   i2 = __shfl_down_sync(0xffffffffu, idx, o);
        if (v2 < v || (v2 == v && i2 < idx)) { v = v2; idx = i2; }
    }
    if (lane == 0) { red[w] = v; redi[w] = idx; }
    __syncthreads();
    if (w == 0) {
        v = red[lane]; idx = redi[lane];
        #pragma unroll
        for (int o = 16; o; o >>= 1) {
            float v2 = __shfl_down_sync(0xffffffffu, v, o);
            int   i2 = __shfl_down_sync(0xffffffffu, idx, o);
            if (v2 < v || (v2 == v && i2 < idx)) { v = v2; idx = i2; }
        }
        if (lane == 0) { red[0] = v; redi[0] = idx; }
    }
    __syncthreads();
    *ov = red[0]; *oi = redi[0];
    __syncthreads();
}

// ---------------- kernel 2: all scalars / reductions (one block, 1024 thr) ----------------
__global__ void k2_scalars(const float* __restrict__ z,
                           const float* __restrict__ usages,
                           const float* __restrict__ beta,
                           const float* __restrict__ gamma,
                           const float* __restrict__ temp,
                           float* __restrict__ out) {
    __shared__ float red[32];
    __shared__ int redi[32];
    const int tid = threadIdx.x;
    const float tempv = temp[0];
    float* out_us = out + 3 + (size_t)KP * DP;

    // ||z||^2
    float acc = 0.f;
    for (int i = tid; i < DP; i += 1024) { float v = z[i]; acc += v * v; }
    float znorm2 = block_sum(acc, red);
    float rz = rsqrtf(znorm2);

    // logits + max
    float mx = -INFINITY;
    for (int i = tid; i < KP; i += 1024) {
        float l = tempv * g_dot[i] * rz * rsqrtf(g_pn2[i]);
        g_logits[i] = l;
        mx = fmaxf(mx, l);
    }
    float maxl = block_max(mx, red);

    float x = (-maxl - beta[0]) / gamma[0];
    float u = 1.f / (1.f + expf(-x));
    int evict = (u >= THRESHF) ? 1 : 0;

    // local argmax of logits2 (fused into branch loops)
    float mv2 = -INFINITY; int mi2 = 0;

    if (evict) {
        // argmin usages
        float mv = INFINITY; int mi = 0;
        for (int i = tid; i < KP; i += 1024) {
            float uv = usages[i];
            if (uv < mv) { mv = uv; mi = i; }
        }
        float bv; int bidx;
        block_argmin(mv, mi, red, redi, &bv, &bidx);

        for (int i = tid; i < KP; i += 1024) {
            float l2, nu;
            if (i == KP - 1) {
                l2 = tempv * znorm2 * rz * rz;  // temp * <zhat,zhat>
                nu = 1.0f;
            } else {
                int src = (i < bidx) ? i : i + 1;
                l2 = g_logits[src];
                nu = usages[src];
            }
            g_l2[i] = l2;
            out_us[i] = nu * DECAYF;
            if (l2 > mv2) { mv2 = l2; mi2 = i; }
        }
        if (tid == 0) { g_evict = 1; g_evict_idx = bidx; }
    } else {
        float se = 0.f;
        for (int i = tid; i < KP; i += 1024) se += expf(g_logits[i] - maxl);
        float sumexp = block_sum(se, red);

        for (int i = tid; i < KP; i += 1024) {
            float y = expf(g_logits[i] - maxl) / sumexp;
            float delta = y * (1.f - u);
            float us = usages[i];
            float a = delta / (delta + us);
            float b = us / (us + delta);
            g_a[i] = a; g_b[i] = b;
            out_us[i] = (us + delta) * DECAYF;
            // analytic logits2: new_p = a*z + b*p
            float dotn = a * znorm2 + b * g_dot[i];
            float nn2 = a * a * znorm2 + 2.f * a * b * g_dot[i] + b * b * g_pn2[i];
            float l2 = tempv * dotn * rz * rsqrtf(nn2);
            g_l2[i] = l2;
            if (l2 > mv2) { mv2 = l2; mi2 = i; }
        }
        if (tid == 0) { g_evict = 0; g_evict_idx = 0; }
    }
    __syncthreads();

    float m2; int lab;
    block_argmax(mv2, mi2, red, redi, &m2, &lab);

    float s2 = 0.f;
    for (int i = tid; i < KP; i += 1024) s2 += expf(g_l2[i] - m2);
    float sum2 = block_sum(s2, red);

    if (tid == 0) {
        float l2lab = g_l2[lab];
        out[0] = logf(sum2) + m2 - l2lab;  // -log_softmax at label
        out[1] = (float)lab;
        out[2] = u;
    }
}

// ---------------- kernel 3: write new prototypes (128 MB) ----------------
// Reverse row order (tail of P freshest in L2 after k1) + evict-first stores
// (__stcs) so the 128 MB of output doesn't displace P from L2 before we read it.
__global__ void k3_write(const float* __restrict__ z,
                         const float* __restrict__ p,
                         float* __restrict__ out) {
    int row = KP - 1 - blockIdx.x;
    float* orow = out + 3 + (size_t)row * DP;
    if (g_evict) {
        const float* src;
        if (row == KP - 1) {
            src = z;
        } else {
            int idx = g_evict_idx;
            src = p + (size_t)((row < idx) ? row : row + 1) * DP;
        }
        for (int j = threadIdx.x; j < DP; j += blockDim.x)
            __stcs(orow + j, src[j]);
    } else {
        float a = g_a[row], b = g_b[row];
        const float* pr = p + (size_t)row * DP;
        for (int j = threadIdx.x; j < DP; j += blockDim.x)
            __stcs(orow + j, fmaf(a, z[j], b * pr[j]));
    }
}

extern "C" void kernel_launch(void* const* d_in, const int* in_sizes, int n_in,
                              void* d_out, int out_size) {
    const float* z     = (const float*)d_in[0];
    const float* p     = (const float*)d_in[1];
    const float* us    = (const float*)d_in[2];
    const float* beta  = (const float*)d_in[3];
    const float* gamma = (const float*)d_in[4];
    const float* temp  = (const float*)d_in[5];
    float* out = (float*)d_out;

    k1_dots<<<KP / 8, 256>>>(z, p);
    k2_scalars<<<1, 1024>>>(z, us, beta, gamma, temp, out);
    k3_write<<<KP, 256>>>(z, p, out);
}

// round 4
// speedup vs baseline: 1.1507x; 1.1507x over previous
#include <cuda_runtime.h>
#include <math.h>

#define KP 16384
#define DP 2048
#define DECAYF 0.99f
#define THRESHF 0.5f

// __device__ scratch (no allocations allowed)
__device__ float g_dot[KP];     // z . p_i
__device__ float g_pn2[KP];     // ||p_i||^2
__device__ float g_a[KP];       // EMA coef of z (cold path)
__device__ float g_b[KP];       // EMA coef of p (cold path)
__device__ int   g_evict;
__device__ int   g_evict_idx;

// ---------------- kernel 1: per-row dot + norm, 2 rows per warp ----------------
__global__ void k1_dots(const float* __restrict__ z, const float* __restrict__ p) {
    __shared__ float4 zs[DP / 4];
    for (int i = threadIdx.x; i < DP / 4; i += blockDim.x)
        zs[i] = ((const float4*)z)[i];
    __syncthreads();
    int warp = threadIdx.x >> 5, lane = threadIdx.x & 31;
    int row0 = (blockIdx.x << 4) + (warp << 1);  // 8 warps * 2 rows = 16 rows/block
    const float4* p0 = (const float4*)(p + (size_t)row0 * DP);
    const float4* p1 = p0 + (DP / 4);
    float d0 = 0.f, n0 = 0.f, d1 = 0.f, n1 = 0.f;
    #pragma unroll
    for (int k = 0; k < 16; ++k) {
        float4 a = p0[lane + k * 32];
        float4 b = p1[lane + k * 32];
        float4 zv = zs[lane + k * 32];
        d0 += a.x * zv.x + a.y * zv.y + a.z * zv.z + a.w * zv.w;
        n0 += a.x * a.x + a.y * a.y + a.z * a.z + a.w * a.w;
        d1 += b.x * zv.x + b.y * zv.y + b.z * zv.z + b.w * zv.w;
        n1 += b.x * b.x + b.y * b.y + b.z * b.z + b.w * b.w;
    }
    #pragma unroll
    for (int o = 16; o; o >>= 1) {
        d0 += __shfl_down_sync(0xffffffffu, d0, o);
        n0 += __shfl_down_sync(0xffffffffu, n0, o);
        d1 += __shfl_down_sync(0xffffffffu, d1, o);
        n1 += __shfl_down_sync(0xffffffffu, n1, o);
    }
    if (lane == 0) {
        g_dot[row0] = d0; g_pn2[row0] = n0;
        g_dot[row0 + 1] = d1; g_pn2[row0 + 1] = n1;
    }
}

// ---------------- block reduction helpers (blockDim = 1024) ----------------
__device__ __forceinline__ float block_sum(float v, float* red) {
    int lane = threadIdx.x & 31, w = threadIdx.x >> 5;
    #pragma unroll
    for (int o = 16; o; o >>= 1) v += __shfl_down_sync(0xffffffffu, v, o);
    if (lane == 0) red[w] = v;
    __syncthreads();
    if (w == 0) {
        v = red[lane];
        #pragma unroll
        for (int o = 16; o; o >>= 1) v += __shfl_down_sync(0xffffffffu, v, o);
        if (lane == 0) red[0] = v;
    }
    __syncthreads();
    float r = red[0];
    __syncthreads();
    return r;
}

__device__ __forceinline__ float block_max(float v, float* red) {
    int lane = threadIdx.x & 31, w = threadIdx.x >> 5;
    #pragma unroll
    for (int o = 16; o; o >>= 1) v = fmaxf(v, __shfl_down_sync(0xffffffffu, v, o));
    if (lane == 0) red[w] = v;
    __syncthreads();
    if (w == 0) {
        v = red[lane];
        #pragma unroll
        for (int o = 16; o; o >>= 1) v = fmaxf(v, __shfl_down_sync(0xffffffffu, v, o));
        if (lane == 0) red[0] = v;
    }
    __syncthreads();
    float r = red[0];
    __syncthreads();
    return r;
}

// argmax, first-occurrence tie-break
__device__ __forceinline__ void block_argmax(float v, int idx, float* red, int* redi,
                                             float* ov, int* oi) {
    int lane = threadIdx.x & 31, w = threadIdx.x >> 5;
    #pragma unroll
    for (int o = 16; o; o >>= 1) {
        float v2 = __shfl_down_sync(0xffffffffu, v, o);
        int   i2 = __shfl_down_sync(0xffffffffu, idx, o);
        if (v2 > v || (v2 == v && i2 < idx)) { v = v2; idx = i2; }
    }
    if (lane == 0) { red[w] = v; redi[w] = idx; }
    __syncthreads();
    if (w == 0) {
        v = red[lane]; idx = redi[lane];
        #pragma unroll
        for (int o = 16; o; o >>= 1) {
            float v2 = __shfl_down_sync(0xffffffffu, v, o);
            int   i2 = __shfl_down_sync(0xffffffffu, idx, o);
            if (v2 > v || (v2 == v && i2 < idx)) { v = v2; idx = i2; }
        }
        if (lane == 0) { red[0] = v; redi[0] = idx; }
    }
    __syncthreads();
    *ov = red[0]; *oi = redi[0];
    __syncthreads();
}

// argmin, first-occurrence tie-break
__device__ __forceinline__ void block_argmin(float v, int idx, float* red, int* redi,
                                             float* ov, int* oi) {
    int lane = threadIdx.x & 31, w = threadIdx.x >> 5;
    #pragma unroll
    for (int o = 16; o; o >>= 1) {
        float v2 = __shfl_down_sync(0xffffffffu, v, o);
        int   i2 = __shfl_down_sync(0xffffffffu, idx, o);
        if (v2 < v || (v2 == v && i2 < idx)) { v = v2; idx = i2; }
    }
    if (lane == 0) { red[w] = v; redi[w] = idx; }
    __syncthreads();
    if (w == 0) {
        v = red[lane]; idx = redi[lane];
        #pragma unroll
        for (int o = 16; o; o >>= 1) {
            float v2 = __shfl_down_sync(0xffffffffu, v, o);
            int   i2 = __shfl_down_sync(0xffffffffu, idx, o);
            if (v2 < v || (v2 == v && i2 < idx)) { v = v2; idx = i2; }
        }
        if (lane == 0) { red[0] = v; redi[0] = idx; }
    }
    __syncthreads();
    *ov = red[0]; *oi = redi[0];
    __syncthreads();
}

// ---------------- kernel 2: register-resident scalars (1 block, 1024 thr) ----------------
// Thread t owns contiguous elements [t*16, t*16+16). All K-length passes run on
// registers; one boundary element per thread exchanged through smem for the
// shifted (evict) read. EMA branch (cold for this input) reloads from global.
__global__ void __launch_bounds__(1024, 1)
k2_scalars(const float* __restrict__ z,
           const float* __restrict__ usages,
           const float* __restrict__ beta,
           const float* __restrict__ gamma,
           const float* __restrict__ temp,
           float* __restrict__ out) {
    __shared__ float red[32];
    __shared__ int redi[32];
    __shared__ float s_bL[1025];  // first logit of each thread (+pad)
    __shared__ float s_bU[1025];  // first usage of each thread
    const int tid = threadIdx.x;
    const float tempv = temp[0];
    const int base = tid * 16;
    float* out_us = out + 3 + (size_t)KP * DP;

    // ||z||^2 (2048 elems, 2 per thread)
    float acc = 0.f;
    {
        float v0 = z[tid], v1 = z[tid + 1024];
        acc = v0 * v0 + v1 * v1;
    }
    float znorm2 = block_sum(acc, red);
    float rz = rsqrtf(znorm2);

    // load dot/pn2 (float4), compute logits into regs, track max
    float L[16], U[16];
    float mx = -INFINITY;
    #pragma unroll
    for (int q = 0; q < 4; ++q) {
        float4 dv = ((const float4*)g_dot)[tid * 4 + q];
        float4 nv = ((const float4*)g_pn2)[tid * 4 + q];
        L[q * 4 + 0] = tempv * dv.x * rz * rsqrtf(nv.x);
        L[q * 4 + 1] = tempv * dv.y * rz * rsqrtf(nv.y);
        L[q * 4 + 2] = tempv * dv.z * rz * rsqrtf(nv.z);
        L[q * 4 + 3] = tempv * dv.w * rz * rsqrtf(nv.w);
        float4 uv = ((const float4*)usages)[tid * 4 + q];
        U[q * 4 + 0] = uv.x; U[q * 4 + 1] = uv.y;
        U[q * 4 + 2] = uv.z; U[q * 4 + 3] = uv.w;
    }
    #pragma unroll
    for (int j = 0; j < 16; ++j) mx = fmaxf(mx, L[j]);
    float maxl = block_max(mx, red);

    float x = (-maxl - beta[0]) / gamma[0];
    float u = 1.f / (1.f + expf(-x));
    int evict = (u >= THRESHF) ? 1 : 0;

    if (evict) {
        // argmin usages (ascending j -> first occurrence within thread)
        float mv = INFINITY; int mi = 0;
        #pragma unroll
        for (int j = 0; j < 16; ++j) {
            if (U[j] < mv) { mv = U[j]; mi = base + j; }
        }
        float bv; int bidx;
        block_argmin(mv, mi, red, redi, &bv, &bidx);

        // boundary exchange: each thread's first element
        s_bL[tid] = L[0];
        s_bU[tid] = U[0];
        __syncthreads();

        // pass 1: shifted logits2 + new usages + argmax(l2)
        float mv2 = -INFINITY; int mi2 = 0;
        #pragma unroll
        for (int j = 0; j < 16; ++j) {
            int i = base + j;
            float l2, nu;
            if (i == KP - 1) {
                l2 = tempv * znorm2 * rz * rz;
                nu = 1.0f;
            } else if (i < bidx) {
                l2 = L[j]; nu = U[j];
            } else if (j < 15) {
                l2 = L[j + 1]; nu = U[j + 1];
            } else {
                l2 = s_bL[tid + 1]; nu = s_bU[tid + 1];
            }
            out_us[i] = nu * DECAYF;
            if (l2 > mv2) { mv2 = l2; mi2 = i; }
        }
        float m2; int lab;
        block_argmax(mv2, mi2, red, redi, &m2, &lab);

        // pass 2: logsumexp (recompute shifted l2 from regs)
        float s2 = 0.f;
        #pragma unroll
        for (int j = 0; j < 16; ++j) {
            int i = base + j;
            float l2;
            if (i == KP - 1)      l2 = tempv * znorm2 * rz * rz;
            else if (i < bidx)    l2 = L[j];
            else if (j < 15)      l2 = L[j + 1];
            else                  l2 = s_bL[tid + 1];
            s2 += expf(l2 - m2);
        }
        float sum2 = block_sum(s2, red);

        if (tid == 0) {
            out[0] = logf(sum2);  // m2 - l2[lab] == 0
            out[1] = (float)lab;
            out[2] = u;
            g_evict = 1; g_evict_idx = bidx;
        }
    } else {
        // EMA branch (cold path): softmax over L, coefs to global for k3
        float se = 0.f;
        #pragma unroll
        for (int j = 0; j < 16; ++j) se += expf(L[j] - maxl);
        float sumexp = block_sum(se, red);

        float mv2 = -INFINITY; int mi2 = 0;
        float A[16], B[16];
        #pragma unroll
        for (int q = 0; q < 4; ++q) {
            float4 dv = ((const float4*)g_dot)[tid * 4 + q];
            float4 nv = ((const float4*)g_pn2)[tid * 4 + q];
            float dvv[4] = {dv.x, dv.y, dv.z, dv.w};
            float nvv[4] = {nv.x, nv.y, nv.z, nv.w};
            #pragma unroll
            for (int r = 0; r < 4; ++r) {
                int j = q * 4 + r;
                int i = base + j;
                float y = expf(L[j] - maxl) / sumexp;
                float delta = y * (1.f - u);
                float us = U[j];
                float a = delta / (delta + us);
                float b = us / (us + delta);
                A[j] = a; B[j] = b;
                out_us[i] = (us + delta) * DECAYF;
                float dotn = a * znorm2 + b * dvv[r];
                float nn2 = a * a * znorm2 + 2.f * a * b * dvv[r] + b * b * nvv[r];
                float l2 = tempv * dotn * rz * rsqrtf(nn2);
                L[j] = l2;  // reuse L regs for logits2
                if (l2 > mv2) { mv2 = l2; mi2 = i; }
            }
        }
        #pragma unroll
        for (int j = 0; j < 16; ++j) { g_a[base + j] = A[j]; g_b[base + j] = B[j]; }

        float m2; int lab;
        block_argmax(mv2, mi2, red, redi, &m2, &lab);

        float s2 = 0.f;
        #pragma unroll
        for (int j = 0; j < 16; ++j) s2 += expf(L[j] - m2);
        float sum2 = block_sum(s2, red);

        if (tid == 0) {
            out[0] = logf(sum2);
            out[1] = (float)lab;
            out[2] = u;
            g_evict = 0; g_evict_idx = 0;
        }
    }
}

// ---------------- kernel 3: write new prototypes (128 MB) ----------------
// Reverse row order (tail of P freshest in L2 after k1), float4 loads, plain
// scalar stores (out+3 is only 4B-aligned).
__global__ void k3_write(const float* __restrict__ z,
                         const float* __restrict__ p,
                         float* __restrict__ out) {
    int row = KP - 1 - blockIdx.x;
    float* orow = out + 3 + (size_t)row * DP;
    int q = threadIdx.x;  // 256 threads, 2 float4 each
    if (g_evict) {
        const float4* src4;
        if (row == KP - 1) {
            src4 = (const float4*)z;
        } else {
            int idx = g_evict_idx;
            src4 = (const float4*)(p + (size_t)((row < idx) ? row : row + 1) * DP);
        }
        float4 v0 = src4[q];
        float4 v1 = src4[q + 256];
        orow[4 * q + 0] = v0.x; orow[4 * q + 1] = v0.y;
        orow[4 * q + 2] = v0.z; orow[4 * q + 3] = v0.w;
        orow[4 * (q + 256) + 0] = v1.x; orow[4 * (q + 256) + 1] = v1.y;
        orow[4 * (q + 256) + 2] = v1.z; orow[4 * (q + 256) + 3] = v1.w;
    } else {
        float a = g_a[row], b = g_b[row];
        const float4* pr4 = (const float4*)(p + (size_t)row * DP);
        const float4* z4 = (const float4*)z;
        float4 pv0 = pr4[q], zv0 = z4[q];
        float4 pv1 = pr4[q + 256], zv1 = z4[q + 256];
        orow[4 * q + 0] = fmaf(a, zv0.x, b * pv0.x);
        orow[4 * q + 1] = fmaf(a, zv0.y, b * pv0.y);
        orow[4 * q + 2] = fmaf(a, zv0.z, b * pv0.z);
        orow[4 * q + 3] = fmaf(a, zv0.w, b * pv0.w);
        orow[4 * (q + 256) + 0] = fmaf(a, zv1.x, b * pv1.x);
        orow[4 * (q + 256) + 1] = fmaf(a, zv1.y, b * pv1.y);
        orow[4 * (q + 256) + 2] = fmaf(a, zv1.z, b * pv1.z);
        orow[4 * (q + 256) + 3] = fmaf(a, zv1.w, b * pv1.w);
    }
}

extern "C" void kernel_launch(void* const* d_in, const int* in_sizes, int n_in,
                              void* d_out, int out_size) {
    const float* z     = (const float*)d_in[0];
    const float* p     = (const float*)d_in[1];
    const float* us    = (const float*)d_in[2];
    const float* beta  = (const float*)d_in[3];
    const float* gamma = (const float*)d_in[4];
    const float* temp  = (const float*)d_in[5];
    float* out = (float*)d_out;

    k1_dots<<<KP / 16, 256>>>(z, p);
    k2_scalars<<<1, 1024>>>(z, us, beta, gamma, temp, out);
    k3_write<<<KP, 256>>>(z, p, out);
}

// round 5
// speedup vs baseline: 1.2341x; 1.0725x over previous
#include <cuda_runtime.h>
#include <math.h>

#define KP 16384
#define DP 2048
#define DECAYF 0.99f
#define THRESHF 0.5f

// __device__ scratch (no allocations allowed)
__device__ float g_dot[KP];     // z . p_i
__device__ float g_pn2[KP];     // ||p_i||^2
__device__ float g_a[KP];       // EMA coef of z (cold path)
__device__ float g_b[KP];       // EMA coef of p (cold path)
__device__ int   g_evict;
__device__ int   g_evict_idx;

// ---------------- kernel 1: per-row dot + norm (R1 version — best measured) ----------------
__global__ void k1_dots(const float* __restrict__ z, const float* __restrict__ p) {
    __shared__ float4 zs[DP / 4];
    for (int i = threadIdx.x; i < DP / 4; i += blockDim.x)
        zs[i] = ((const float4*)z)[i];
    __syncthreads();
    int warp = threadIdx.x >> 5, lane = threadIdx.x & 31;
    int row = (blockIdx.x << 3) + warp;  // 8 warps/block
    const float4* pr = (const float4*)(p + (size_t)row * DP);
    float dot = 0.f, n2 = 0.f;
    #pragma unroll
    for (int i = lane; i < DP / 4; i += 32) {
        float4 a = pr[i], b = zs[i];
        dot += a.x * b.x + a.y * b.y + a.z * b.z + a.w * b.w;
        n2  += a.x * a.x + a.y * a.y + a.z * a.z + a.w * a.w;
    }
    #pragma unroll
    for (int o = 16; o; o >>= 1) {
        dot += __shfl_down_sync(0xffffffffu, dot, o);
        n2  += __shfl_down_sync(0xffffffffu, n2, o);
    }
    if (lane == 0) { g_dot[row] = dot; g_pn2[row] = n2; }
}

// ---------------- block reduction helpers (blockDim = 1024) ----------------
__device__ __forceinline__ float block_sum(float v, float* red) {
    int lane = threadIdx.x & 31, w = threadIdx.x >> 5;
    #pragma unroll
    for (int o = 16; o; o >>= 1) v += __shfl_down_sync(0xffffffffu, v, o);
    if (lane == 0) red[w] = v;
    __syncthreads();
    if (w == 0) {
        v = red[lane];
        #pragma unroll
        for (int o = 16; o; o >>= 1) v += __shfl_down_sync(0xffffffffu, v, o);
        if (lane == 0) red[0] = v;
    }
    __syncthreads();
    float r = red[0];
    __syncthreads();
    return r;
}

__device__ __forceinline__ float block_max(float v, float* red) {
    int lane = threadIdx.x & 31, w = threadIdx.x >> 5;
    #pragma unroll
    for (int o = 16; o; o >>= 1) v = fmaxf(v, __shfl_down_sync(0xffffffffu, v, o));
    if (lane == 0) red[w] = v;
    __syncthreads();
    if (w == 0) {
        v = red[lane];
        #pragma unroll
        for (int o = 16; o; o >>= 1) v = fmaxf(v, __shfl_down_sync(0xffffffffu, v, o));
        if (lane == 0) red[0] = v;
    }
    __syncthreads();
    float r = red[0];
    __syncthreads();
    return r;
}

// argmax, first-occurrence tie-break
__device__ __forceinline__ void block_argmax(float v, int idx, float* red, int* redi,
                                             float* ov, int* oi) {
    int lane = threadIdx.x & 31, w = threadIdx.x >> 5;
    #pragma unroll
    for (int o = 16; o; o >>= 1) {
        float v2 = __shfl_down_sync(0xffffffffu, v, o);
        int   i2 = __shfl_down_sync(0xffffffffu, idx, o);
        if (v2 > v || (v2 == v && i2 < idx)) { v = v2; idx = i2; }
    }
    if (lane == 0) { red[w] = v; redi[w] = idx; }
    __syncthreads();
    if (w == 0) {
        v = red[lane]; idx = redi[lane];
        #pragma unroll
        for (int o = 16; o; o >>= 1) {
            float v2 = __shfl_down_sync(0xffffffffu, v, o);
            int   i2 = __shfl_down_sync(0xffffffffu, idx, o);
            if (v2 > v || (v2 == v && i2 < idx)) { v = v2; idx = i2; }
        }
        if (lane == 0) { red[0] = v; redi[0] = idx; }
    }
    __syncthreads();
    *ov = red[0]; *oi = redi[0];
    __syncthreads();
}

// argmin, first-occurrence tie-break
__device__ __forceinline__ void block_argmin(float v, int idx, float* red, int* redi,
                                             float* ov, int* oi) {
    int lane = threadIdx.x & 31, w = threadIdx.x >> 5;
    #pragma unroll
    for (int o = 16; o; o >>= 1) {
        float v2 = __shfl_down_sync(0xffffffffu, v, o);
        int   i2 = __shfl_down_sync(0xffffffffu, idx, o);
        if (v2 < v || (v2 == v && i2 < idx)) { v = v2; idx = i2; }
    }
    if (lane == 0) { red[w] = v; redi[w] = idx; }
    __syncthreads();
    if (w == 0) {
        v = red[lane]; idx = redi[lane];
        #pragma unroll
        for (int o = 16; o; o >>= 1) {
            float v2 = __shfl_down_sync(0xffffffffu, v, o);
            int   i2 = __shfl_down_sync(0xffffffffu, idx, o);
            if (v2 < v || (v2 == v && i2 < idx)) { v = v2; idx = i2; }
        }
        if (lane == 0) { red[0] = v; redi[0] = idx; }
    }
    __syncthreads();
    *ov = red[0]; *oi = redi[0];
    __syncthreads();
}

// ---------------- kernel 2: register-resident scalars (1 block, 1024 thr) ----------------
__global__ void __launch_bounds__(1024, 1)
k2_scalars(const float* __restrict__ z,
           const float* __restrict__ usages,
           const float* __restrict__ beta,
           const float* __restrict__ gamma,
           const float* __restrict__ temp,
           float* __restrict__ out) {
    __shared__ float red[32];
    __shared__ int redi[32];
    __shared__ float s_bL[1025];  // first logit of each thread (+pad)
    __shared__ float s_bU[1025];  // first usage of each thread
    const int tid = threadIdx.x;
    const float tempv = temp[0];
    const int base = tid * 16;
    float* out_us = out + 3 + (size_t)KP * DP;

    // ||z||^2 (2048 elems, 2 per thread)
    float acc = 0.f;
    {
        float v0 = z[tid], v1 = z[tid + 1024];
        acc = v0 * v0 + v1 * v1;
    }
    float znorm2 = block_sum(acc, red);
    float rz = rsqrtf(znorm2);

    // load dot/pn2 (float4), compute logits into regs, track max
    float L[16], U[16];
    float mx = -INFINITY;
    #pragma unroll
    for (int q = 0; q < 4; ++q) {
        float4 dv = ((const float4*)g_dot)[tid * 4 + q];
        float4 nv = ((const float4*)g_pn2)[tid * 4 + q];
        L[q * 4 + 0] = tempv * dv.x * rz * rsqrtf(nv.x);
        L[q * 4 + 1] = tempv * dv.y * rz * rsqrtf(nv.y);
        L[q * 4 + 2] = tempv * dv.z * rz * rsqrtf(nv.z);
        L[q * 4 + 3] = tempv * dv.w * rz * rsqrtf(nv.w);
        float4 uv = ((const float4*)usages)[tid * 4 + q];
        U[q * 4 + 0] = uv.x; U[q * 4 + 1] = uv.y;
        U[q * 4 + 2] = uv.z; U[q * 4 + 3] = uv.w;
    }
    #pragma unroll
    for (int j = 0; j < 16; ++j) mx = fmaxf(mx, L[j]);
    float maxl = block_max(mx, red);

    float x = (-maxl - beta[0]) / gamma[0];
    float u = 1.f / (1.f + expf(-x));
    int evict = (u >= THRESHF) ? 1 : 0;

    if (evict) {
        // argmin usages
        float mv = INFINITY; int mi = 0;
        #pragma unroll
        for (int j = 0; j < 16; ++j) {
            if (U[j] < mv) { mv = U[j]; mi = base + j; }
        }
        float bv; int bidx;
        block_argmin(mv, mi, red, redi, &bv, &bidx);

        // boundary exchange: each thread's first element
        s_bL[tid] = L[0];
        s_bU[tid] = U[0];
        __syncthreads();

        // pass 1: shifted logits2 + new usages + argmax(l2)
        float mv2 = -INFINITY; int mi2 = 0;
        #pragma unroll
        for (int j = 0; j < 16; ++j) {
            int i = base + j;
            float l2, nu;
            if (i == KP - 1) {
                l2 = tempv * znorm2 * rz * rz;
                nu = 1.0f;
            } else if (i < bidx) {
                l2 = L[j]; nu = U[j];
            } else if (j < 15) {
                l2 = L[j + 1]; nu = U[j + 1];
            } else {
                l2 = s_bL[tid + 1]; nu = s_bU[tid + 1];
            }
            out_us[i] = nu * DECAYF;
            if (l2 > mv2) { mv2 = l2; mi2 = i; }
        }
        float m2; int lab;
        block_argmax(mv2, mi2, red, redi, &m2, &lab);

        // pass 2: logsumexp (recompute shifted l2 from regs)
        float s2 = 0.f;
        #pragma unroll
        for (int j = 0; j < 16; ++j) {
            int i = base + j;
            float l2;
            if (i == KP - 1)      l2 = tempv * znorm2 * rz * rz;
            else if (i < bidx)    l2 = L[j];
            else if (j < 15)      l2 = L[j + 1];
            else                  l2 = s_bL[tid + 1];
            s2 += expf(l2 - m2);
        }
        float sum2 = block_sum(s2, red);

        if (tid == 0) {
            out[0] = logf(sum2);  // m2 - l2[lab] == 0
            out[1] = (float)lab;
            out[2] = u;
            g_evict = 1; g_evict_idx = bidx;
        }
    } else {
        // EMA branch (cold path)
        float se = 0.f;
        #pragma unroll
        for (int j = 0; j < 16; ++j) se += expf(L[j] - maxl);
        float sumexp = block_sum(se, red);

        float mv2 = -INFINITY; int mi2 = 0;
        float A[16], B[16];
        #pragma unroll
        for (int q = 0; q < 4; ++q) {
            float4 dv = ((const float4*)g_dot)[tid * 4 + q];
            float4 nv = ((const float4*)g_pn2)[tid * 4 + q];
            float dvv[4] = {dv.x, dv.y, dv.z, dv.w};
            float nvv[4] = {nv.x, nv.y, nv.z, nv.w};
            #pragma unroll
            for (int r = 0; r < 4; ++r) {
                int j = q * 4 + r;
                int i = base + j;
                float y = expf(L[j] - maxl) / sumexp;
                float delta = y * (1.f - u);
                float us = U[j];
                float a = delta / (delta + us);
                float b = us / (us + delta);
                A[j] = a; B[j] = b;
                out_us[i] = (us + delta) * DECAYF;
                float dotn = a * znorm2 + b * dvv[r];
                float nn2 = a * a * znorm2 + 2.f * a * b * dvv[r] + b * b * nvv[r];
                float l2 = tempv * dotn * rz * rsqrtf(nn2);
                L[j] = l2;  // reuse L regs for logits2
                if (l2 > mv2) { mv2 = l2; mi2 = i; }
            }
        }
        #pragma unroll
        for (int j = 0; j < 16; ++j) { g_a[base + j] = A[j]; g_b[base + j] = B[j]; }

        float m2; int lab;
        block_argmax(mv2, mi2, red, redi, &m2, &lab);

        float s2 = 0.f;
        #pragma unroll
        for (int j = 0; j < 16; ++j) s2 += expf(L[j] - m2);
        float sum2 = block_sum(s2, red);

        if (tid == 0) {
            out[0] = logf(sum2);
            out[1] = (float)lab;
            out[2] = u;
            g_evict = 0; g_evict_idx = 0;
        }
    }
}

// ---------------- kernel 3: write new prototypes (128 MB), fully 128-bit ----------------
// Output row base (out+3+row*2048) is misaligned by 3 floats, but out+4 is 16B
// aligned. Each thread does ONE aligned LDG.128 at chunk t, passes its .x to the
// left neighbor via smem, and does ONE aligned STG.128 at orow+1+4t covering
// elements [1+4t, 4+4t]. Thread 511 writes the 4 edge scalars (0, 2045..2047).
// Reverse row order so the tail of P (freshest in L2 after k1) hits.
__global__ void __launch_bounds__(512, 4)
k3_write(const float* __restrict__ z,
         const float* __restrict__ p,
         float* __restrict__ out) {
    __shared__ float s_x[512];
    const int row = KP - 1 - blockIdx.x;
    const int t = threadIdx.x;
    float* orow = out + 3 + (size_t)row * DP;

    float4 v;
    if (g_evict) {
        const float4* src4;
        if (row == KP - 1) {
            src4 = (const float4*)z;
        } else {
            int idx = g_evict_idx;
            src4 = (const float4*)(p + (size_t)((row < idx) ? row : row + 1) * DP);
        }
        v = src4[t];
    } else {
        float a = g_a[row], b = g_b[row];
        float4 pv = ((const float4*)(p + (size_t)row * DP))[t];
        float4 zv = ((const float4*)z)[t];
        v.x = fmaf(a, zv.x, b * pv.x);
        v.y = fmaf(a, zv.y, b * pv.y);
        v.z = fmaf(a, zv.z, b * pv.z);
        v.w = fmaf(a, zv.w, b * pv.w);
    }

    s_x[t] = v.x;
    __syncthreads();

    if (t < 511) {
        float4 w;
        w.x = v.y; w.y = v.z; w.z = v.w; w.w = s_x[t + 1];
        *(float4*)(orow + 1 + 4 * t) = w;
    } else {
        orow[2045] = v.y;
        orow[2046] = v.z;
        orow[2047] = v.w;
        orow[0] = s_x[0];
    }
}

extern "C" void kernel_launch(void* const* d_in, const int* in_sizes, int n_in,
                              void* d_out, int out_size) {
    const float* z     = (const float*)d_in[0];
    const float* p     = (const float*)d_in[1];
    const float* us    = (const float*)d_in[2];
    const float* beta  = (const float*)d_in[3];
    const float* gamma = (const float*)d_in[4];
    const float* temp  = (const float*)d_in[5];
    float* out = (float*)d_out;

    k1_dots<<<KP / 8, 256>>>(z, p);
    k2_scalars<<<1, 1024>>>(z, us, beta, gamma, temp, out);
    k3_write<<<KP, 512>>>(z, p, out);
}

// round 6
// speedup vs baseline: 1.3355x; 1.0821x over previous
#include <cuda_runtime.h>
#include <math.h>

#define KP 16384
#define DP 2048
#define DECAYF 0.99f
#define THRESHF 0.5f

// __device__ scratch (no allocations allowed)
__device__ float g_dot[KP];     // z . p_i (original row indexing)
__device__ float g_pn2[KP];     // ||p_i||^2
__device__ float g_a[KP];       // EMA coef of z (cold path)
__device__ float g_b[KP];       // EMA coef of p (cold path)
__device__ int   g_evict;
__device__ int   g_evict_idx;

// ---------------- block reduction helpers (1024-thr kernels) ----------------
__device__ __forceinline__ float block_sum(float v, float* red) {
    int lane = threadIdx.x & 31, w = threadIdx.x >> 5;
    #pragma unroll
    for (int o = 16; o; o >>= 1) v += __shfl_down_sync(0xffffffffu, v, o);
    if (lane == 0) red[w] = v;
    __syncthreads();
    if (w == 0) {
        v = red[lane];
        #pragma unroll
        for (int o = 16; o; o >>= 1) v += __shfl_down_sync(0xffffffffu, v, o);
        if (lane == 0) red[0] = v;
    }
    __syncthreads();
    float r = red[0];
    __syncthreads();
    return r;
}

__device__ __forceinline__ float block_max(float v, float* red) {
    int lane = threadIdx.x & 31, w = threadIdx.x >> 5;
    #pragma unroll
    for (int o = 16; o; o >>= 1) v = fmaxf(v, __shfl_down_sync(0xffffffffu, v, o));
    if (lane == 0) red[w] = v;
    __syncthreads();
    if (w == 0) {
        v = red[lane];
        #pragma unroll
        for (int o = 16; o; o >>= 1) v = fmaxf(v, __shfl_down_sync(0xffffffffu, v, o));
        if (lane == 0) red[0] = v;
    }
    __syncthreads();
    float r = red[0];
    __syncthreads();
    return r;
}

__device__ __forceinline__ void block_argmax(float v, int idx, float* red, int* redi,
                                             float* ov, int* oi) {
    int lane = threadIdx.x & 31, w = threadIdx.x >> 5;
    #pragma unroll
    for (int o = 16; o; o >>= 1) {
        float v2 = __shfl_down_sync(0xffffffffu, v, o);
        int   i2 = __shfl_down_sync(0xffffffffu, idx, o);
        if (v2 > v || (v2 == v && i2 < idx)) { v = v2; idx = i2; }
    }
    if (lane == 0) { red[w] = v; redi[w] = idx; }
    __syncthreads();
    if (w == 0) {
        v = red[lane]; idx = redi[lane];
        #pragma unroll
        for (int o = 16; o; o >>= 1) {
            float v2 = __shfl_down_sync(0xffffffffu, v, o);
            int   i2 = __shfl_down_sync(0xffffffffu, idx, o);
            if (v2 > v || (v2 == v && i2 < idx)) { v = v2; idx = i2; }
        }
        if (lane == 0) { red[0] = v; redi[0] = idx; }
    }
    __syncthreads();
    *ov = red[0]; *oi = redi[0];
    __syncthreads();
}

__device__ __forceinline__ void block_argmin(float v, int idx, float* red, int* redi,
                                             float* ov, int* oi) {
    int lane = threadIdx.x & 31, w = threadIdx.x >> 5;
    #pragma unroll
    for (int o = 16; o; o >>= 1) {
        float v2 = __shfl_down_sync(0xffffffffu, v, o);
        int   i2 = __shfl_down_sync(0xffffffffu, idx, o);
        if (v2 < v || (v2 == v && i2 < idx)) { v = v2; idx = i2; }
    }
    if (lane == 0) { red[w] = v; redi[w] = idx; }
    __syncthreads();
    if (w == 0) {
        v = red[lane]; idx = redi[lane];
        #pragma unroll
        for (int o = 16; o; o >>= 1) {
            float v2 = __shfl_down_sync(0xffffffffu, v, o);
            int   i2 = __shfl_down_sync(0xffffffffu, idx, o);
            if (v2 < v || (v2 == v && i2 < idx)) { v = v2; idx = i2; }
        }
        if (lane == 0) { red[0] = v; redi[0] = idx; }
    }
    __syncthreads();
    *ov = red[0]; *oi = redi[0];
    __syncthreads();
}

// ---------------- kernel 0: argmin(usages) -> g_evict_idx (branch-independent) ----------
__global__ void __launch_bounds__(1024, 1)
k0_argmin(const float* __restrict__ usages) {
    __shared__ float red[32];
    __shared__ int redi[32];
    const int tid = threadIdx.x;
    const int base = tid * 16;
    float mv = INFINITY; int mi = 0;
    #pragma unroll
    for (int q = 0; q < 4; ++q) {
        float4 uv = ((const float4*)usages)[tid * 4 + q];
        float u4[4] = {uv.x, uv.y, uv.z, uv.w};
        #pragma unroll
        for (int r = 0; r < 4; ++r) {
            if (u4[r] < mv) { mv = u4[r]; mi = base + q * 4 + r; }
        }
    }
    float bv; int bidx;
    block_argmin(mv, mi, red, redi, &bv, &bidx);
    if (tid == 0) g_evict_idx = bidx;
}

// ---------------- fused kernel 1: dot/norm of source row + speculative evict write ------
// Output row b gets P row (b<bidx ? b : b+1); row KP-1 gets z. While the source
// row is in registers we compute its dot/||.||^2 (stored at the SOURCE index, so
// g_dot/g_pn2 cover all original rows; block KP handles the evicted row bidx).
// Store uses the alignment-shift trick: one aligned STG.128 per thread.
__global__ void __launch_bounds__(512, 4)
k1_fused(const float* __restrict__ z,
         const float* __restrict__ p,
         float* __restrict__ out) {
    __shared__ float s_x[512];
    __shared__ float rd[16], rn[16];
    const int b = blockIdx.x;
    const int t = threadIdx.x;
    const int lane = t & 31, w = t >> 5;
    const int bidx = g_evict_idx;
    const float4* z4 = (const float4*)z;

    if (b == KP) {  // dot/norm of evicted row only (needed for logits max)
        const float4* pr = (const float4*)(p + (size_t)bidx * DP);
        float4 v = pr[t], zv = z4[t];
        float dot = v.x * zv.x + v.y * zv.y + v.z * zv.z + v.w * zv.w;
        float n2  = v.x * v.x + v.y * v.y + v.z * v.z + v.w * v.w;
        #pragma unroll
        for (int o = 16; o; o >>= 1) {
            dot += __shfl_down_sync(0xffffffffu, dot, o);
            n2  += __shfl_down_sync(0xffffffffu, n2, o);
        }
        if (lane == 0) { rd[w] = dot; rn[w] = n2; }
        __syncthreads();
        if (w == 0 && lane < 16) {
            dot = rd[lane]; n2 = rn[lane];
            #pragma unroll
            for (int o = 8; o; o >>= 1) {
                dot += __shfl_down_sync(0xffffu, dot, o);
                n2  += __shfl_down_sync(0xffffu, n2, o);
            }
            if (lane == 0) { g_dot[bidx] = dot; g_pn2[bidx] = n2; }
        }
        return;
    }

    float4 v;
    if (b == KP - 1) {
        v = z4[t];  // appended z row; no dot needed
    } else {
        int s = (b < bidx) ? b : b + 1;
        const float4* pr = (const float4*)(p + (size_t)s * DP);
        v = pr[t];
        float4 zv = z4[t];
        float dot = v.x * zv.x + v.y * zv.y + v.z * zv.z + v.w * zv.w;
        float n2  = v.x * v.x + v.y * v.y + v.z * v.z + v.w * v.w;
        #pragma unroll
        for (int o = 16; o; o >>= 1) {
            dot += __shfl_down_sync(0xffffffffu, dot, o);
            n2  += __shfl_down_sync(0xffffffffu, n2, o);
        }
        if (lane == 0) { rd[w] = dot; rn[w] = n2; }
        __syncthreads();
        if (w == 0 && lane < 16) {
            dot = rd[lane]; n2 = rn[lane];
            #pragma unroll
            for (int o = 8; o; o >>= 1) {
                dot += __shfl_down_sync(0xffffu, dot, o);
                n2  += __shfl_down_sync(0xffffu, n2, o);
            }
            if (lane == 0) { g_dot[s] = dot; g_pn2[s] = n2; }
        }
    }

    // speculative evict-branch store (aligned-shift)
    float* orow = out + 3 + (size_t)b * DP;
    s_x[t] = v.x;
    __syncthreads();
    if (t < 511) {
        float4 wv;
        wv.x = v.y; wv.y = v.z; wv.z = v.w; wv.w = s_x[t + 1];
        *(float4*)(orow + 1 + 4 * t) = wv;
    } else {
        orow[2045] = v.y;
        orow[2046] = v.z;
        orow[2047] = v.w;
        orow[0] = s_x[0];
    }
}

// ---------------- kernel 2: register-resident scalars (1 block, 1024 thr) ----------------
__global__ void __launch_bounds__(1024, 1)
k2_scalars(const float* __restrict__ z,
           const float* __restrict__ usages,
           const float* __restrict__ beta,
           const float* __restrict__ gamma,
           const float* __restrict__ temp,
           float* __restrict__ out) {
    __shared__ float red[32];
    __shared__ int redi[32];
    __shared__ float s_bL[1025];
    __shared__ float s_bU[1025];
    const int tid = threadIdx.x;
    const float tempv = temp[0];
    const int base = tid * 16;
    float* out_us = out + 3 + (size_t)KP * DP;

    // ||z||^2
    float acc;
    {
        float v0 = z[tid], v1 = z[tid + 1024];
        acc = v0 * v0 + v1 * v1;
    }
    float znorm2 = block_sum(acc, red);
    float rz = rsqrtf(znorm2);

    // logits + max (register-resident)
    float L[16], U[16];
    float mx = -INFINITY;
    #pragma unroll
    for (int q = 0; q < 4; ++q) {
        float4 dv = ((const float4*)g_dot)[tid * 4 + q];
        float4 nv = ((const float4*)g_pn2)[tid * 4 + q];
        L[q * 4 + 0] = tempv * dv.x * rz * rsqrtf(nv.x);
        L[q * 4 + 1] = tempv * dv.y * rz * rsqrtf(nv.y);
        L[q * 4 + 2] = tempv * dv.z * rz * rsqrtf(nv.z);
        L[q * 4 + 3] = tempv * dv.w * rz * rsqrtf(nv.w);
        float4 uv = ((const float4*)usages)[tid * 4 + q];
        U[q * 4 + 0] = uv.x; U[q * 4 + 1] = uv.y;
        U[q * 4 + 2] = uv.z; U[q * 4 + 3] = uv.w;
    }
    #pragma unroll
    for (int j = 0; j < 16; ++j) mx = fmaxf(mx, L[j]);
    float maxl = block_max(mx, red);

    float x = (-maxl - beta[0]) / gamma[0];
    float u = 1.f / (1.f + expf(-x));
    int evict = (u >= THRESHF) ? 1 : 0;

    if (evict) {
        int bidx = g_evict_idx;

        s_bL[tid] = L[0];
        s_bU[tid] = U[0];
        __syncthreads();

        float mv2 = -INFINITY; int mi2 = 0;
        #pragma unroll
        for (int j = 0; j < 16; ++j) {
            int i = base + j;
            float l2, nu;
            if (i == KP - 1) {
                l2 = tempv * znorm2 * rz * rz;
                nu = 1.0f;
            } else if (i < bidx) {
                l2 = L[j]; nu = U[j];
            } else if (j < 15) {
                l2 = L[j + 1]; nu = U[j + 1];
            } else {
                l2 = s_bL[tid + 1]; nu = s_bU[tid + 1];
            }
            out_us[i] = nu * DECAYF;
            if (l2 > mv2) { mv2 = l2; mi2 = i; }
        }
        float m2; int lab;
        block_argmax(mv2, mi2, red, redi, &m2, &lab);

        float s2 = 0.f;
        #pragma unroll
        for (int j = 0; j < 16; ++j) {
            int i = base + j;
            float l2;
            if (i == KP - 1)      l2 = tempv * znorm2 * rz * rz;
            else if (i < bidx)    l2 = L[j];
            else if (j < 15)      l2 = L[j + 1];
            else                  l2 = s_bL[tid + 1];
            s2 += expf(l2 - m2);
        }
        float sum2 = block_sum(s2, red);

        if (tid == 0) {
            out[0] = logf(sum2);  // m2 - l2[lab] == 0
            out[1] = (float)lab;
            out[2] = u;
            g_evict = 1;
        }
    } else {
        // EMA branch (cold path): k1_fused's speculative output will be fixed by k3_fix
        float se = 0.f;
        #pragma unroll
        for (int j = 0; j < 16; ++j) se += expf(L[j] - maxl);
        float sumexp = block_sum(se, red);

        float mv2 = -INFINITY; int mi2 = 0;
        float A[16], B[16];
        #pragma unroll
        for (int q = 0; q < 4; ++q) {
            float4 dv = ((const float4*)g_dot)[tid * 4 + q];
            float4 nv = ((const float4*)g_pn2)[tid * 4 + q];
            float dvv[4] = {dv.x, dv.y, dv.z, dv.w};
            float nvv[4] = {nv.x, nv.y, nv.z, nv.w};
            #pragma unroll
            for (int r = 0; r < 4; ++r) {
                int j = q * 4 + r;
                int i = base + j;
                float y = expf(L[j] - maxl) / sumexp;
                float delta = y * (1.f - u);
                float us = U[j];
                float a = delta / (delta + us);
                float bb = us / (us + delta);
                A[j] = a; B[j] = bb;
                out_us[i] = (us + delta) * DECAYF;
                float dotn = a * znorm2 + bb * dvv[r];
                float nn2 = a * a * znorm2 + 2.f * a * bb * dvv[r] + bb * bb * nvv[r];
                float l2 = tempv * dotn * rz * rsqrtf(nn2);
                L[j] = l2;
                if (l2 > mv2) { mv2 = l2; mi2 = i; }
            }
        }
        #pragma unroll
        for (int j = 0; j < 16; ++j) { g_a[base + j] = A[j]; g_b[base + j] = B[j]; }

        float m2; int lab;
        block_argmax(mv2, mi2, red, redi, &m2, &lab);

        float s2 = 0.f;
        #pragma unroll
        for (int j = 0; j < 16; ++j) s2 += expf(L[j] - m2);
        float sum2 = block_sum(s2, red);

        if (tid == 0) {
            out[0] = logf(sum2);
            out[1] = (float)lab;
            out[2] = u;
            g_evict = 0;
        }
    }
}

// ---------------- kernel 3: EMA fix-up (no-op on the evict path) ----------------
// 2048 blocks x 8 rows. When evict (hot case) every block exits immediately.
__global__ void __launch_bounds__(512, 4)
k3_fix(const float* __restrict__ z,
       const float* __restrict__ p,
       float* __restrict__ out) {
    if (g_evict) return;
    __shared__ float s_x[512];
    const int t = threadIdx.x;
    const float4* z4 = (const float4*)z;
    float4 zv = z4[t];
    for (int r = 0; r < 8; ++r) {
        int row = blockIdx.x * 8 + r;
        float a = g_a[row], bb = g_b[row];
        float4 pv = ((const float4*)(p + (size_t)row * DP))[t];
        float4 v;
        v.x = fmaf(a, zv.x, bb * pv.x);
        v.y = fmaf(a, zv.y, bb * pv.y);
        v.z = fmaf(a, zv.z, bb * pv.z);
        v.w = fmaf(a, zv.w, bb * pv.w);
        float* orow = out + 3 + (size_t)row * DP;
        __syncthreads();
        s_x[t] = v.x;
        __syncthreads();
        if (t < 511) {
            float4 wv;
            wv.x = v.y; wv.y = v.z; wv.z = v.w; wv.w = s_x[t + 1];
            *(float4*)(orow + 1 + 4 * t) = wv;
        } else {
            orow[2045] = v.y;
            orow[2046] = v.z;
            orow[2047] = v.w;
            orow[0] = s_x[0];
        }
    }
}

extern "C" void kernel_launch(void* const* d_in, const int* in_sizes, int n_in,
                              void* d_out, int out_size) {
    const float* z     = (const float*)d_in[0];
    const float* p     = (const float*)d_in[1];
    const float* us    = (const float*)d_in[2];
    const float* beta  = (const float*)d_in[3];
    const float* gamma = (const float*)d_in[4];
    const float* temp  = (const float*)d_in[5];
    float* out = (float*)d_out;

    k0_argmin<<<1, 1024>>>(us);
    k1_fused<<<KP + 1, 512>>>(z, p, out);
    k2_scalars<<<1, 1024>>>(z, us, beta, gamma, temp, out);
    k3_fix<<<2048, 512>>>(z, p, out);
}

// round 8
// speedup vs baseline: 1.5401x; 1.1532x over previous
#include <cuda_runtime.h>
#include <math.h>

#define KP 16384
#define DP 2048
#define DECAYF 0.99f
#define THRESHF 0.5f

// __device__ scratch (no allocations allowed)
__device__ float g_dot[KP];     // z . p_i (original row indexing)
__device__ float g_pn2[KP];     // ||p_i||^2
__device__ float g_a[KP];       // EMA coef of z (cold path)
__device__ float g_b[KP];       // EMA coef of p (cold path)
__device__ int   g_evict;
__device__ int   g_evict_idx;

// ---------------- block reduction helpers (1024-thr kernels) ----------------
__device__ __forceinline__ float block_sum(float v, float* red) {
    int lane = threadIdx.x & 31, w = threadIdx.x >> 5;
    #pragma unroll
    for (int o = 16; o; o >>= 1) v += __shfl_down_sync(0xffffffffu, v, o);
    if (lane == 0) red[w] = v;
    __syncthreads();
    if (w == 0) {
        v = red[lane];
        #pragma unroll
        for (int o = 16; o; o >>= 1) v += __shfl_down_sync(0xffffffffu, v, o);
        if (lane == 0) red[0] = v;
    }
    __syncthreads();
    float r = red[0];
    __syncthreads();
    return r;
}

__device__ __forceinline__ float block_max(float v, float* red) {
    int lane = threadIdx.x & 31, w = threadIdx.x >> 5;
    #pragma unroll
    for (int o = 16; o; o >>= 1) v = fmaxf(v, __shfl_down_sync(0xffffffffu, v, o));
    if (lane == 0) red[w] = v;
    __syncthreads();
    if (w == 0) {
        v = red[lane];
        #pragma unroll
        for (int o = 16; o; o >>= 1) v = fmaxf(v, __shfl_down_sync(0xffffffffu, v, o));
        if (lane == 0) red[0] = v;
    }
    __syncthreads();
    float r = red[0];
    __syncthreads();
    return r;
}

__device__ __forceinline__ void block_argmax(float v, int idx, float* red, int* redi,
                                             float* ov, int* oi) {
    int lane = threadIdx.x & 31, w = threadIdx.x >> 5;
    #pragma unroll
    for (int o = 16; o; o >>= 1) {
        float v2 = __shfl_down_sync(0xffffffffu, v, o);
        int   i2 = __shfl_down_sync(0xffffffffu, idx, o);
        if (v2 > v || (v2 == v && i2 < idx)) { v = v2; idx = i2; }
    }
    if (lane == 0) { red[w] = v; redi[w] = idx; }
    __syncthreads();
    if (w == 0) {
        v = red[lane]; idx = redi[lane];
        #pragma unroll
        for (int o = 16; o; o >>= 1) {
            float v2 = __shfl_down_sync(0xffffffffu, v, o);
            int   i2 = __shfl_down_sync(0xffffffffu, idx, o);
            if (v2 > v || (v2 == v && i2 < idx)) { v = v2; idx = i2; }
        }
        if (lane == 0) { red[0] = v; redi[0] = idx; }
    }
    __syncthreads();
    *ov = red[0]; *oi = redi[0];
    __syncthreads();
}

__device__ __forceinline__ void block_argmin(float v, int idx, float* red, int* redi,
                                             float* ov, int* oi) {
    int lane = threadIdx.x & 31, w = threadIdx.x >> 5;
    #pragma unroll
    for (int o = 16; o; o >>= 1) {
        float v2 = __shfl_down_sync(0xffffffffu, v, o);
        int   i2 = __shfl_down_sync(0xffffffffu, idx, o);
        if (v2 < v || (v2 == v && i2 < idx)) { v = v2; idx = i2; }
    }
    if (lane == 0) { red[w] = v; redi[w] = idx; }
    __syncthreads();
    if (w == 0) {
        v = red[lane]; idx = redi[lane];
        #pragma unroll
        for (int o = 16; o; o >>= 1) {
            float v2 = __shfl_down_sync(0xffffffffu, v, o);
            int   i2 = __shfl_down_sync(0xffffffffu, idx, o);
            if (v2 < v || (v2 == v && i2 < idx)) { v = v2; idx = i2; }
        }
        if (lane == 0) { red[0] = v; redi[0] = idx; }
    }
    __syncthreads();
    *ov = red[0]; *oi = redi[0];
    __syncthreads();
}

// ---------------- kernel 0: argmin(usages) -> g_evict_idx ----------------
__global__ void __launch_bounds__(1024, 1)
k0_argmin(const float* __restrict__ usages) {
    __shared__ float red[32];
    __shared__ int redi[32];
    const int tid = threadIdx.x;
    const int base = tid * 16;
    float mv = INFINITY; int mi = 0;
    #pragma unroll
    for (int q = 0; q < 4; ++q) {
        float4 uv = ((const float4*)usages)[tid * 4 + q];
        float u4[4] = {uv.x, uv.y, uv.z, uv.w};
        #pragma unroll
        for (int r = 0; r < 4; ++r) {
            if (u4[r] < mv) { mv = u4[r]; mi = base + q * 4 + r; }
        }
    }
    float bv; int bidx;
    block_argmin(mv, mi, red, redi, &bv, &bidx);
    if (tid == 0) g_evict_idx = bidx;
}

// ---------------- fused kernel: warp-per-half-row, MLP=8 ----------------
// Grid: 4096 blocks of 256 threads (8 warps) -> 32768 half-rows = 16384 output
// rows; block 4096 computes the evicted row's dot/norm only.
// Output row b = source P row (b<bidx ? b : b+1); row KP-1 = z.
// Store uses the alignment-shift: out+4 is 16B aligned, each chunk's float4
// store needs the NEXT chunk's .x (via intra-warp shfl / smem at half seam).
__global__ void __launch_bounds__(256, 4)
k1_fused(const float* __restrict__ z,
         const float* __restrict__ p,
         float* __restrict__ out) {
    __shared__ float4 zs[DP / 4];            // 8 KB staged z
    __shared__ float s_d[8], s_n[8], s_x0[8];
    const int warp = threadIdx.x >> 5, lane = threadIdx.x & 31;
    const int bidx = g_evict_idx;

    // stage z
    for (int i = threadIdx.x; i < DP / 4; i += 256)
        zs[i] = ((const float4*)z)[i];
    __syncthreads();

    if (blockIdx.x == 4096) {  // evicted row's dot/norm
        if (warp < 2) {
            const float4* src = (const float4*)(p + (size_t)bidx * DP) + warp * 256;
            float dot = 0.f, n2 = 0.f;
            #pragma unroll
            for (int k = 0; k < 8; ++k) {
                float4 v = src[lane + 32 * k];
                float4 zc = zs[warp * 256 + lane + 32 * k];
                dot += v.x * zc.x + v.y * zc.y + v.z * zc.z + v.w * zc.w;
                n2  += v.x * v.x + v.y * v.y + v.z * v.z + v.w * v.w;
            }
            #pragma unroll
            for (int o = 16; o; o >>= 1) {
                dot += __shfl_down_sync(0xffffffffu, dot, o);
                n2  += __shfl_down_sync(0xffffffffu, n2, o);
            }
            if (lane == 0) { s_d[warp] = dot; s_n[warp] = n2; }
        }
        __syncthreads();
        if (warp == 0 && lane == 0) {
            g_dot[bidx] = s_d[0] + s_d[1];
            g_pn2[bidx] = s_n[0] + s_n[1];
        }
        return;
    }

    const int rowOut = blockIdx.x * 4 + (warp >> 1);
    const int half = warp & 1;
    const bool is_z = (rowOut == KP - 1);
    const int s = (rowOut < bidx) ? rowOut : rowOut + 1;
    const int cbase = half * 256;

    const float4* src = (is_z ? (const float4*)zs
                              : (const float4*)(p + (size_t)s * DP)) + cbase;

    float4 v[8];
    #pragma unroll
    for (int k = 0; k < 8; ++k) v[k] = src[lane + 32 * k];

    // dot / norm (computed for P-sourced rows only)
    if (!is_z) {
        float dot = 0.f, n2 = 0.f;
        #pragma unroll
        for (int k = 0; k < 8; ++k) {
            float4 zc = zs[cbase + lane + 32 * k];
            dot += v[k].x * zc.x + v[k].y * zc.y + v[k].z * zc.z + v[k].w * zc.w;
            n2  += v[k].x * v[k].x + v[k].y * v[k].y + v[k].z * v[k].z + v[k].w * v[k].w;
        }
        #pragma unroll
        for (int o = 16; o; o >>= 1) {
            dot += __shfl_down_sync(0xffffffffu, dot, o);
            n2  += __shfl_down_sync(0xffffffffu, n2, o);
        }
        if (lane == 0) { s_d[warp] = dot; s_n[warp] = n2; }
    }

    // neighbor-x for misaligned stores: sh[k] = v[k].x of lane+1 (lane31 -> lane0)
    float sh[8];
    #pragma unroll
    for (int k = 0; k < 8; ++k)
        sh[k] = __shfl_sync(0xffffffffu, v[k].x, (lane + 1) & 31);
    if (lane == 0) s_x0[warp] = v[0].x;
    __syncthreads();

    if (!is_z && half == 0 && lane == 0) {
        g_dot[s] = s_d[warp] + s_d[warp + 1];
        g_pn2[s] = s_n[warp] + s_n[warp + 1];
    }

    // stores: chunk c covers out elems [4c..4c+3]; we store [1+4c..4+4c] aligned
    float* orow = out + 3 + (size_t)rowOut * DP;
    #pragma unroll
    for (int k = 0; k < 8; ++k) {
        int c = cbase + lane + 32 * k;
        if (c == DP / 4 - 1) {  // last chunk of row: 3 tail scalars
            orow[2045] = v[k].y;
            orow[2046] = v[k].z;
            orow[2047] = v[k].w;
        } else {
            float nx;
            if (lane < 31)      nx = sh[k];
            else if (k < 7)     nx = sh[k + 1];
            else                nx = s_x0[warp + 1];  // half seam (half==0 only here)
            float4 wv;
            wv.x = v[k].y; wv.y = v[k].z; wv.z = v[k].w; wv.w = nx;
            *(float4*)(orow + 1 + 4 * c) = wv;
        }
    }
    if (half == 0 && lane == 0) orow[0] = v[0].x;
}

// ---------------- kernel 2: register-resident scalars (1 block, 1024 thr) ----------------
__global__ void __launch_bounds__(1024, 1)
k2_scalars(const float* __restrict__ z,
           const float* __restrict__ usages,
           const float* __restrict__ beta,
           const float* __restrict__ gamma,
           const float* __restrict__ temp,
           float* __restrict__ out) {
    __shared__ float red[32];
    __shared__ int redi[32];
    __shared__ float s_bL[1025];
    __shared__ float s_bU[1025];
    const int tid = threadIdx.x;
    const float tempv = temp[0];
    const int base = tid * 16;
    float* out_us = out + 3 + (size_t)KP * DP;

    float acc;
    {
        float v0 = z[tid], v1 = z[tid + 1024];
        acc = v0 * v0 + v1 * v1;
    }
    float znorm2 = block_sum(acc, red);
    float rz = rsqrtf(znorm2);

    float L[16], U[16];
    float mx = -INFINITY;
    #pragma unroll
    for (int q = 0; q < 4; ++q) {
        float4 dv = ((const float4*)g_dot)[tid * 4 + q];
        float4 nv = ((const float4*)g_pn2)[tid * 4 + q];
        L[q * 4 + 0] = tempv * dv.x * rz * rsqrtf(nv.x);
        L[q * 4 + 1] = tempv * dv.y * rz * rsqrtf(nv.y);
        L[q * 4 + 2] = tempv * dv.z * rz * rsqrtf(nv.z);
        L[q * 4 + 3] = tempv * dv.w * rz * rsqrtf(nv.w);
        float4 uv = ((const float4*)usages)[tid * 4 + q];
        U[q * 4 + 0] = uv.x; U[q * 4 + 1] = uv.y;
        U[q * 4 + 2] = uv.z; U[q * 4 + 3] = uv.w;
    }
    #pragma unroll
    for (int j = 0; j < 16; ++j) mx = fmaxf(mx, L[j]);
    float maxl = block_max(mx, red);

    float x = (-maxl - beta[0]) / gamma[0];
    float u = 1.f / (1.f + expf(-x));
    int evict = (u >= THRESHF) ? 1 : 0;

    if (evict) {
        int bidx = g_evict_idx;

        s_bL[tid] = L[0];
        s_bU[tid] = U[0];
        __syncthreads();

        float mv2 = -INFINITY; int mi2 = 0;
        #pragma unroll
        for (int j = 0; j < 16; ++j) {
            int i = base + j;
            float l2, nu;
            if (i == KP - 1) {
                l2 = tempv * znorm2 * rz * rz;
                nu = 1.0f;
            } else if (i < bidx) {
                l2 = L[j]; nu = U[j];
            } else if (j < 15) {
                l2 = L[j + 1]; nu = U[j + 1];
            } else {
                l2 = s_bL[tid + 1]; nu = s_bU[tid + 1];
            }
            out_us[i] = nu * DECAYF;
            if (l2 > mv2) { mv2 = l2; mi2 = i; }
        }
        float m2; int lab;
        block_argmax(mv2, mi2, red, redi, &m2, &lab);

        float s2 = 0.f;
        #pragma unroll
        for (int j = 0; j < 16; ++j) {
            int i = base + j;
            float l2;
            if (i == KP - 1)      l2 = tempv * znorm2 * rz * rz;
            else if (i < bidx)    l2 = L[j];
            else if (j < 15)      l2 = L[j + 1];
            else                  l2 = s_bL[tid + 1];
            s2 += expf(l2 - m2);
        }
        float sum2 = block_sum(s2, red);

        if (tid == 0) {
            out[0] = logf(sum2);  // m2 - l2[lab] == 0
            out[1] = (float)lab;
            out[2] = u;
            g_evict = 1;
        }
    } else {
        float se = 0.f;
        #pragma unroll
        for (int j = 0; j < 16; ++j) se += expf(L[j] - maxl);
        float sumexp = block_sum(se, red);

        float mv2 = -INFINITY; int mi2 = 0;
        float A[16], B[16];
        #pragma unroll
        for (int q = 0; q < 4; ++q) {
            float4 dv = ((const float4*)g_dot)[tid * 4 + q];
            float4 nv = ((const float4*)g_pn2)[tid * 4 + q];
            float dvv[4] = {dv.x, dv.y, dv.z, dv.w};
            float nvv[4] = {nv.x, nv.y, nv.z, nv.w};
            #pragma unroll
            for (int r = 0; r < 4; ++r) {
                int j = q * 4 + r;
                int i = base + j;
                float y = expf(L[j] - maxl) / sumexp;
                float delta = y * (1.f - u);
                float us = U[j];
                float a = delta / (delta + us);
                float bb = us / (us + delta);
                A[j] = a; B[j] = bb;
                out_us[i] = (us + delta) * DECAYF;
                float dotn = a * znorm2 + bb * dvv[r];
                float nn2 = a * a * znorm2 + 2.f * a * bb * dvv[r] + bb * bb * nvv[r];
                float l2 = tempv * dotn * rz * rsqrtf(nn2);
                L[j] = l2;
                if (l2 > mv2) { mv2 = l2; mi2 = i; }
            }
        }
        #pragma unroll
        for (int j = 0; j < 16; ++j) { g_a[base + j] = A[j]; g_b[base + j] = B[j]; }

        float m2; int lab;
        block_argmax(mv2, mi2, red, redi, &m2, &lab);

        float s2 = 0.f;
        #pragma unroll
        for (int j = 0; j < 16; ++j) s2 += expf(L[j] - m2);
        float sum2 = block_sum(s2, red);

        if (tid == 0) {
            out[0] = logf(sum2);
            out[1] = (float)lab;
            out[2] = u;
            g_evict = 0;
        }
    }
}

// ---------------- kernel 3: EMA fix-up (no-op on the evict path) ----------------
// 256 blocks x 512 threads, grid-stride over rows. Hot case: immediate exit.
__global__ void __launch_bounds__(512, 4)
k3_fix(const float* __restrict__ z,
       const float* __restrict__ p,
       float* __restrict__ out) {
    if (g_evict) return;
    __shared__ float s_x[512];
    const int t = threadIdx.x;
    const float4* z4 = (const float4*)z;
    float4 zv = z4[t];
    for (int row = blockIdx.x; row < KP; row += 256) {
        float a = g_a[row], bb = g_b[row];
        float4 pv = ((const float4*)(p + (size_t)row * DP))[t];
        float4 v;
        v.x = fmaf(a, zv.x, bb * pv.x);
        v.y = fmaf(a, zv.y, bb * pv.y);
        v.z = fmaf(a, zv.z, bb * pv.z);
        v.w = fmaf(a, zv.w, bb * pv.w);
        float* orow = out + 3 + (size_t)row * DP;
        __syncthreads();
        s_x[t] = v.x;
        __syncthreads();
        if (t < 511) {
            float4 wv;
            wv.x = v.y; wv.y = v.z; wv.z = v.w; wv.w = s_x[t + 1];
            *(float4*)(orow + 1 + 4 * t) = wv;
        } else {
            orow[2045] = v.y;
            orow[2046] = v.z;
            orow[2047] = v.w;
            orow[0] = s_x[0];
        }
    }
}

extern "C" void kernel_launch(void* const* d_in, const int* in_sizes, int n_in,
                              void* d_out, int out_size) {
    const float* z     = (const float*)d_in[0];
    const float* p     = (const float*)d_in[1];
    const float* us    = (const float*)d_in[2];
    const float* beta  = (const float*)d_in[3];
    const float* gamma = (const float*)d_in[4];
    const float* temp  = (const float*)d_in[5];
    float* out = (float*)d_out;

    k0_argmin<<<1, 1024>>>(us);
    k1_fused<<<4097, 256>>>(z, p, out);
    k2_scalars<<<1, 1024>>>(z, us, beta, gamma, temp, out);
    k3_fix<<<256, 512>>>(z, p, out);
}

// round 9
// speedup vs baseline: 1.5941x; 1.0351x over previous
#include <cuda_runtime.h>
#include <math.h>

#define KP 16384
#define DP 2048
#define DECAYF 0.99f
#define THRESHF 0.5f

// __device__ scratch (no allocations allowed)
__device__ float g_dot[KP];     // z . p_i (original row indexing)
__device__ float g_pn2[KP];     // ||p_i||^2
__device__ float g_a[KP];       // EMA coef of z (cold path)
__device__ float g_b[KP];       // EMA coef of p (cold path)
__device__ int   g_evict;
__device__ int   g_evict_idx;

// ---------------- block reduction helpers (1024-thr kernels) ----------------
__device__ __forceinline__ float block_sum(float v, float* red) {
    int lane = threadIdx.x & 31, w = threadIdx.x >> 5;
    #pragma unroll
    for (int o = 16; o; o >>= 1) v += __shfl_down_sync(0xffffffffu, v, o);
    if (lane == 0) red[w] = v;
    __syncthreads();
    if (w == 0) {
        v = red[lane];
        #pragma unroll
        for (int o = 16; o; o >>= 1) v += __shfl_down_sync(0xffffffffu, v, o);
        if (lane == 0) red[0] = v;
    }
    __syncthreads();
    float r = red[0];
    __syncthreads();
    return r;
}

__device__ __forceinline__ float block_max(float v, float* red) {
    int lane = threadIdx.x & 31, w = threadIdx.x >> 5;
    #pragma unroll
    for (int o = 16; o; o >>= 1) v = fmaxf(v, __shfl_down_sync(0xffffffffu, v, o));
    if (lane == 0) red[w] = v;
    __syncthreads();
    if (w == 0) {
        v = red[lane];
        #pragma unroll
        for (int o = 16; o; o >>= 1) v = fmaxf(v, __shfl_down_sync(0xffffffffu, v, o));
        if (lane == 0) red[0] = v;
    }
    __syncthreads();
    float r = red[0];
    __syncthreads();
    return r;
}

__device__ __forceinline__ void block_argmax(float v, int idx, float* red, int* redi,
                                             float* ov, int* oi) {
    int lane = threadIdx.x & 31, w = threadIdx.x >> 5;
    #pragma unroll
    for (int o = 16; o; o >>= 1) {
        float v2 = __shfl_down_sync(0xffffffffu, v, o);
        int   i2 = __shfl_down_sync(0xffffffffu, idx, o);
        if (v2 > v || (v2 == v && i2 < idx)) { v = v2; idx = i2; }
    }
    if (lane == 0) { red[w] = v; redi[w] = idx; }
    __syncthreads();
    if (w == 0) {
        v = red[lane]; idx = redi[lane];
        #pragma unroll
        for (int o = 16; o; o >>= 1) {
            float v2 = __shfl_down_sync(0xffffffffu, v, o);
            int   i2 = __shfl_down_sync(0xffffffffu, idx, o);
            if (v2 > v || (v2 == v && i2 < idx)) { v = v2; idx = i2; }
        }
        if (lane == 0) { red[0] = v; redi[0] = idx; }
    }
    __syncthreads();
    *ov = red[0]; *oi = redi[0];
    __syncthreads();
}

__device__ __forceinline__ void block_argmin(float v, int idx, float* red, int* redi,
                                             float* ov, int* oi) {
    int lane = threadIdx.x & 31, w = threadIdx.x >> 5;
    #pragma unroll
    for (int o = 16; o; o >>= 1) {
        float v2 = __shfl_down_sync(0xffffffffu, v, o);
        int   i2 = __shfl_down_sync(0xffffffffu, idx, o);
        if (v2 < v || (v2 == v && i2 < idx)) { v = v2; idx = i2; }
    }
    if (lane == 0) { red[w] = v; redi[w] = idx; }
    __syncthreads();
    if (w == 0) {
        v = red[lane]; idx = redi[lane];
        #pragma unroll
        for (int o = 16; o; o >>= 1) {
            float v2 = __shfl_down_sync(0xffffffffu, v, o);
            int   i2 = __shfl_down_sync(0xffffffffu, idx, o);
            if (v2 < v || (v2 == v && i2 < idx)) { v = v2; idx = i2; }
        }
        if (lane == 0) { red[0] = v; redi[0] = idx; }
    }
    __syncthreads();
    *ov = red[0]; *oi = redi[0];
    __syncthreads();
}

// ---------------- kernel 0: argmin(usages) -> g_evict_idx ----------------
__global__ void __launch_bounds__(1024, 1)
k0_argmin(const float* __restrict__ usages) {
    __shared__ float red[32];
    __shared__ int redi[32];
    const int tid = threadIdx.x;
    const int base = tid * 16;
    float mv = INFINITY; int mi = 0;
    #pragma unroll
    for (int q = 0; q < 4; ++q) {
        float4 uv = ((const float4*)usages)[tid * 4 + q];
        float u4[4] = {uv.x, uv.y, uv.z, uv.w};
        #pragma unroll
        for (int r = 0; r < 4; ++r) {
            if (u4[r] < mv) { mv = u4[r]; mi = base + q * 4 + r; }
        }
    }
    float bv; int bidx;
    block_argmin(mv, mi, red, redi, &bv, &bidx);
    if (tid == 0) g_evict_idx = bidx;
}

// ---------------- fused kernel: warp-per-FULL-row, MLP=16, pure-shfl seam ----------
// Grid: 4096 row-blocks of 128 threads (4 warps -> 4 rows each) + 1 block for the
// evicted row's dot/norm. Output row b = source P row (b<bidx ? b : b+1); row
// KP-1 = z. Aligned-shift stores: chunk c stores out elems [4c+1..4c+4] with the
// next chunk's .x as .w. For lane<31 that's sh[k]; for lane 31 chunk c+1 is
// lane 0 of batch k+1 -> sh[k+1]. (k=15,lane=31 is the 3-scalar tail.)
__global__ void __launch_bounds__(128, 4)
k1_fused(const float* __restrict__ z,
         const float* __restrict__ p,
         float* __restrict__ out) {
    __shared__ float4 zs[DP / 4];            // 8 KB staged z
    const int warp = threadIdx.x >> 5, lane = threadIdx.x & 31;
    const int bidx = g_evict_idx;

    // stage z (4 float4 per thread)
    #pragma unroll
    for (int i = threadIdx.x; i < DP / 4; i += 128)
        zs[i] = ((const float4*)z)[i];
    __syncthreads();

    if (blockIdx.x == 4096) {  // evicted row's dot/norm (4 warps, quarter each)
        __shared__ float s_d[4], s_n[4];
        const float4* src = (const float4*)(p + (size_t)bidx * DP) + warp * 128;
        float dot = 0.f, n2 = 0.f;
        #pragma unroll
        for (int k = 0; k < 4; ++k) {
            float4 v = src[lane + 32 * k];
            float4 zc = zs[warp * 128 + lane + 32 * k];
            dot += v.x * zc.x + v.y * zc.y + v.z * zc.z + v.w * zc.w;
            n2  += v.x * v.x + v.y * v.y + v.z * v.z + v.w * v.w;
        }
        #pragma unroll
        for (int o = 16; o; o >>= 1) {
            dot += __shfl_down_sync(0xffffffffu, dot, o);
            n2  += __shfl_down_sync(0xffffffffu, n2, o);
        }
        if (lane == 0) { s_d[warp] = dot; s_n[warp] = n2; }
        __syncthreads();
        if (threadIdx.x == 0) {
            g_dot[bidx] = s_d[0] + s_d[1] + s_d[2] + s_d[3];
            g_pn2[bidx] = s_n[0] + s_n[1] + s_n[2] + s_n[3];
        }
        return;
    }

    const int rowOut = blockIdx.x * 4 + warp;
    const bool is_z = (rowOut == KP - 1);
    const int s = (rowOut < bidx) ? rowOut : rowOut + 1;

    const float4* src = is_z ? (const float4*)zs
                             : (const float4*)(p + (size_t)s * DP);

    // 16 loads issued back-to-back
    float4 v[16];
    #pragma unroll
    for (int k = 0; k < 16; ++k) v[k] = src[lane + 32 * k];

    // dot / norm (P-sourced rows only), written directly by lane 0
    if (!is_z) {
        float dot = 0.f, n2 = 0.f;
        #pragma unroll
        for (int k = 0; k < 16; ++k) {
            float4 zc = zs[lane + 32 * k];
            dot += v[k].x * zc.x + v[k].y * zc.y + v[k].z * zc.z + v[k].w * zc.w;
            n2  += v[k].x * v[k].x + v[k].y * v[k].y + v[k].z * v[k].z + v[k].w * v[k].w;
        }
        #pragma unroll
        for (int o = 16; o; o >>= 1) {
            dot += __shfl_down_sync(0xffffffffu, dot, o);
            n2  += __shfl_down_sync(0xffffffffu, n2, o);
        }
        if (lane == 0) { g_dot[s] = dot; g_pn2[s] = n2; }
    }

    // neighbor-x for misaligned stores (pure intra-warp)
    float sh[16];
    #pragma unroll
    for (int k = 0; k < 16; ++k)
        sh[k] = __shfl_sync(0xffffffffu, v[k].x, (lane + 1) & 31);

    float* orow = out + 3 + (size_t)rowOut * DP;
    #pragma unroll
    for (int k = 0; k < 16; ++k) {
        int c = lane + 32 * k;
        if (k == 15 && lane == 31) {  // chunk 511: 3 tail scalars
            orow[2045] = v[k].y;
            orow[2046] = v[k].z;
            orow[2047] = v[k].w;
        } else {
            float nx = (lane < 31) ? sh[k] : sh[k + 1];
            float4 wv;
            wv.x = v[k].y; wv.y = v[k].z; wv.z = v[k].w; wv.w = nx;
            *(float4*)(orow + 1 + 4 * c) = wv;
        }
    }
    if (lane == 0) orow[0] = v[0].x;
}

// ---------------- kernel 2: register-resident scalars (1 block, 1024 thr) ----------------
__global__ void __launch_bounds__(1024, 1)
k2_scalars(const float* __restrict__ z,
           const float* __restrict__ usages,
           const float* __restrict__ beta,
           const float* __restrict__ gamma,
           const float* __restrict__ temp,
           float* __restrict__ out) {
    __shared__ float red[32];
    __shared__ int redi[32];
    __shared__ float s_bL[1025];
    __shared__ float s_bU[1025];
    const int tid = threadIdx.x;
    const float tempv = temp[0];
    const int base = tid * 16;
    float* out_us = out + 3 + (size_t)KP * DP;

    float acc;
    {
        float v0 = z[tid], v1 = z[tid + 1024];
        acc = v0 * v0 + v1 * v1;
    }
    float znorm2 = block_sum(acc, red);
    float rz = rsqrtf(znorm2);

    float L[16], U[16];
    float mx = -INFINITY;
    #pragma unroll
    for (int q = 0; q < 4; ++q) {
        float4 dv = ((const float4*)g_dot)[tid * 4 + q];
        float4 nv = ((const float4*)g_pn2)[tid * 4 + q];
        L[q * 4 + 0] = tempv * dv.x * rz * rsqrtf(nv.x);
        L[q * 4 + 1] = tempv * dv.y * rz * rsqrtf(nv.y);
        L[q * 4 + 2] = tempv * dv.z * rz * rsqrtf(nv.z);
        L[q * 4 + 3] = tempv * dv.w * rz * rsqrtf(nv.w);
        float4 uv = ((const float4*)usages)[tid * 4 + q];
        U[q * 4 + 0] = uv.x; U[q * 4 + 1] = uv.y;
        U[q * 4 + 2] = uv.z; U[q * 4 + 3] = uv.w;
    }
    #pragma unroll
    for (int j = 0; j < 16; ++j) mx = fmaxf(mx, L[j]);
    float maxl = block_max(mx, red);

    float x = (-maxl - beta[0]) / gamma[0];
    float u = 1.f / (1.f + expf(-x));
    int evict = (u >= THRESHF) ? 1 : 0;

    if (evict) {
        int bidx = g_evict_idx;

        s_bL[tid] = L[0];
        s_bU[tid] = U[0];
        __syncthreads();

        float mv2 = -INFINITY; int mi2 = 0;
        #pragma unroll
        for (int j = 0; j < 16; ++j) {
            int i = base + j;
            float l2, nu;
            if (i == KP - 1) {
                l2 = tempv * znorm2 * rz * rz;
                nu = 1.0f;
            } else if (i < bidx) {
                l2 = L[j]; nu = U[j];
            } else if (j < 15) {
                l2 = L[j + 1]; nu = U[j + 1];
            } else {
                l2 = s_bL[tid + 1]; nu = s_bU[tid + 1];
            }
            out_us[i] = nu * DECAYF;
            if (l2 > mv2) { mv2 = l2; mi2 = i; }
        }
        float m2; int lab;
        block_argmax(mv2, mi2, red, redi, &m2, &lab);

        float s2 = 0.f;
        #pragma unroll
        for (int j = 0; j < 16; ++j) {
            int i = base + j;
            float l2;
            if (i == KP - 1)      l2 = tempv * znorm2 * rz * rz;
            else if (i < bidx)    l2 = L[j];
            else if (j < 15)      l2 = L[j + 1];
            else                  l2 = s_bL[tid + 1];
            s2 += expf(l2 - m2);
        }
        float sum2 = block_sum(s2, red);

        if (tid == 0) {
            out[0] = logf(sum2);  // m2 - l2[lab] == 0
            out[1] = (float)lab;
            out[2] = u;
            g_evict = 1;
        }
    } else {
        float se = 0.f;
        #pragma unroll
        for (int j = 0; j < 16; ++j) se += expf(L[j] - maxl);
        float sumexp = block_sum(se, red);

        float mv2 = -INFINITY; int mi2 = 0;
        float A[16], B[16];
        #pragma unroll
        for (int q = 0; q < 4; ++q) {
            float4 dv = ((const float4*)g_dot)[tid * 4 + q];
            float4 nv = ((const float4*)g_pn2)[tid * 4 + q];
            float dvv[4] = {dv.x, dv.y, dv.z, dv.w};
            float nvv[4] = {nv.x, nv.y, nv.z, nv.w};
            #pragma unroll
            for (int r = 0; r < 4; ++r) {
                int j = q * 4 + r;
                int i = base + j;
                float y = expf(L[j] - maxl) / sumexp;
                float delta = y * (1.f - u);
                float us = U[j];
                float a = delta / (delta + us);
                float bb = us / (us + delta);
                A[j] = a; B[j] = bb;
                out_us[i] = (us + delta) * DECAYF;
                float dotn = a * znorm2 + bb * dvv[r];
                float nn2 = a * a * znorm2 + 2.f * a * bb * dvv[r] + bb * bb * nvv[r];
                float l2 = tempv * dotn * rz * rsqrtf(nn2);
                L[j] = l2;
                if (l2 > mv2) { mv2 = l2; mi2 = i; }
            }
        }
        #pragma unroll
        for (int j = 0; j < 16; ++j) { g_a[base + j] = A[j]; g_b[base + j] = B[j]; }

        float m2; int lab;
        block_argmax(mv2, mi2, red, redi, &m2, &lab);

        float s2 = 0.f;
        #pragma unroll
        for (int j = 0; j < 16; ++j) s2 += expf(L[j] - m2);
        float sum2 = block_sum(s2, red);

        if (tid == 0) {
            out[0] = logf(sum2);
            out[1] = (float)lab;
            out[2] = u;
            g_evict = 0;
        }
    }
}

// ---------------- kernel 3: EMA fix-up (no-op on the evict path) ----------------
// 64 blocks x 512 threads, grid-stride over rows. Hot case: immediate exit.
__global__ void __launch_bounds__(512, 4)
k3_fix(const float* __restrict__ z,
       const float* __restrict__ p,
       float* __restrict__ out) {
    if (g_evict) return;
    __shared__ float s_x[512];
    const int t = threadIdx.x;
    const float4* z4 = (const float4*)z;
    float4 zv = z4[t];
    for (int row = blockIdx.x; row < KP; row += 64) {
        float a = g_a[row], bb = g_b[row];
        float4 pv = ((const float4*)(p + (size_t)row * DP))[t];
        float4 v;
        v.x = fmaf(a, zv.x, bb * pv.x);
        v.y = fmaf(a, zv.y, bb * pv.y);
        v.z = fmaf(a, zv.z, bb * pv.z);
        v.w = fmaf(a, zv.w, bb * pv.w);
        float* orow = out + 3 + (size_t)row * DP;
        __syncthreads();
        s_x[t] = v.x;
        __syncthreads();
        if (t < 511) {
            float4 wv;
            wv.x = v.y; wv.y = v.z; wv.z = v.w; wv.w = s_x[t + 1];
            *(float4*)(orow + 1 + 4 * t) = wv;
        } else {
            orow[2045] = v.y;
            orow[2046] = v.z;
            orow[2047] = v.w;
            orow[0] = s_x[0];
        }
    }
}

extern "C" void kernel_launch(void* const* d_in, const int* in_sizes, int n_in,
                              void* d_out, int out_size) {
    const float* z     = (const float*)d_in[0];
    const float* p     = (const float*)d_in[1];
    const float* us    = (const float*)d_in[2];
    const float* beta  = (const float*)d_in[3];
    const float* gamma = (const float*)d_in[4];
    const float* temp  = (const float*)d_in[5];
    float* out = (float*)d_out;

    k0_argmin<<<1, 1024>>>(us);
    k1_fused<<<4097, 128>>>(z, p, out);
    k2_scalars<<<1, 1024>>>(z, us, beta, gamma, temp, out);
    k3_fix<<<64, 512>>>(z, p, out);
}